// round 1
// baseline (speedup 1.0000x reference)
#include <cuda_runtime.h>
#include <cuda_bf16.h>
#include <math.h>

#define VV 50000
#define EE 512
#define HH 512
#define BB 128
#define SS 256
#define OOV 12
#define VEXT (VV + OOV)   // 50012

// ---------------- scratch (device globals; no allocation) ----------------
// offsets in floats
#define OFF_XEMB   0                                 // B*E      = 65536
#define OFF_PREV   (OFF_XEMB + BB*EE)                // B*H
#define OFF_GI     (OFF_PREV + BB*HH)                // B*3H     = 196608
#define OFF_GH     (OFF_GI + BB*3*HH)
#define OFF_STATE  (OFF_GH + BB*3*HH)                // B*H
#define OFF_SATT   (OFF_STATE + BB*HH)               // B*H
#define OFF_ENERGY (OFF_SATT + BB*HH)                // B*S
#define OFF_ATTNW  (OFF_ENERGY + BB*SS)              // B*S
#define OFF_Y      (OFF_ATTNW + BB*SS)               // B*2H
#define OFF_SCOREG (OFF_Y + BB*2*HH)                 // B*V   = 6,400,000
#define OFF_SCOREC (OFF_SCOREG + (size_t)BB*VV)      // B*S
#define OFF_PROBC  (OFF_SCOREC + BB*SS)              // B*S
#define OFF_M      (OFF_PROBC + BB*SS)               // B
#define OFF_Z      (OFF_M + BB)                      // B
#define OFF_PCSUM  (OFF_Z + BB)                      // 1
#define SCRATCH_FLOATS (OFF_PCSUM + 64)

__device__ float g_scratch[SCRATCH_FLOATS];

// ---------------- small generic GEMM:  C[M,N] = A[M,K] @ W[N,K]^T + bias ----
__global__ __launch_bounds__(256)
void gemm_nt_bias(const float* __restrict__ A, int lda,
                  const float* __restrict__ W, int ldw,
                  const float* __restrict__ bias,
                  float* __restrict__ C, int M, int N, int K)
{
    __shared__ float As[16][17];
    __shared__ float Ws[16][17];
    int tx = threadIdx.x, ty = threadIdx.y;
    int m = blockIdx.y * 16 + ty;
    int n = blockIdx.x * 16 + tx;
    float acc = 0.f;
    for (int k0 = 0; k0 < K; k0 += 16) {
        int an = blockIdx.x * 16 + ty;
        As[ty][tx] = (m < M) ? A[m * lda + k0 + tx] : 0.f;
        Ws[ty][tx] = (an < N) ? W[an * ldw + k0 + tx] : 0.f;
        __syncthreads();
#pragma unroll
        for (int k = 0; k < 16; k++) acc += As[ty][k] * Ws[tx][k];
        __syncthreads();
    }
    if (m < M && n < N) C[m * N + n] = acc + (bias ? bias[n] : 0.f);
}

// ---------------- embed gather ----------------
__global__ __launch_bounds__(512)
void gather_embed(const int* __restrict__ idx, const float* __restrict__ tab,
                  float* __restrict__ x)
{
    int b = blockIdx.x, t = threadIdx.x;
    x[b * EE + t] = tab[(long)idx[b] * EE + t];
}

// ---------------- GRU elementwise ----------------
__global__ __launch_bounds__(256)
void gru_kernel(const float* __restrict__ gi, const float* __restrict__ gh,
                const float* __restrict__ prev,
                float* __restrict__ state, float* __restrict__ y,
                float* __restrict__ out_state)
{
    int i = blockIdx.x * 256 + threadIdx.x;   // over B*H
    int b = i / HH, h = i - b * HH;
    const float* gib = gi + b * 3 * HH;
    const float* ghb = gh + b * 3 * HH;
    float i_r = gib[h],            h_r = ghb[h];
    float i_z = gib[HH + h],       h_z = ghb[HH + h];
    float i_n = gib[2 * HH + h],   h_n = ghb[2 * HH + h];
    float r = 1.f / (1.f + expf(-(i_r + h_r)));
    float z = 1.f / (1.f + expf(-(i_z + h_z)));
    float n = tanhf(i_n + r * h_n);
    float st = (1.f - z) * n + z * prev[i];
    state[i] = st;
    y[b * (2 * HH) + h] = st;
    out_state[i] = st;
}

// ---------------- fused: out[r] = sum_n tanh( (A@W^T)[r,n] + add[n] ) * wv[n] ----
// A: [32768, 512] (encoded). Block = 64 rows (all same b), loops all Ntot.
__global__ __launch_bounds__(256)
void fused_tanh_dot(const float* __restrict__ A,
                    const float* __restrict__ W, int ldw,
                    const float* __restrict__ addg, int add_per_b,
                    const float* __restrict__ wvg, int wv_per_b,
                    const int* __restrict__ maskidx,
                    int Ntot, float* __restrict__ outv)
{
    const int row0 = blockIdx.x * 64;
    const int b = row0 >> 8;                 // / S
    __shared__ float Asm[16][68];
    __shared__ float Wsm[16][68];
    __shared__ float addv[64];
    __shared__ float wv[64];
    __shared__ float red[64][17];
    const int tid = threadIdx.x;
    const int ty = tid >> 4, tx = tid & 15;
    float partial[4] = {0.f, 0.f, 0.f, 0.f};

    for (int n0 = 0; n0 < Ntot; n0 += 64) {
        __syncthreads();  // protect addv/wv from prior-tile readers
        if (tid < 64) {
            addv[tid] = add_per_b ? addg[b * Ntot + n0 + tid] : addg[n0 + tid];
            wv[tid]   = wv_per_b  ? wvg[b * Ntot + n0 + tid]  : wvg[n0 + tid];
        }
        float acc[4][4] = {{0.f,0.f,0.f,0.f},{0.f,0.f,0.f,0.f},
                           {0.f,0.f,0.f,0.f},{0.f,0.f,0.f,0.f}};
        for (int k0 = 0; k0 < 512; k0 += 16) {
            __syncthreads();
#pragma unroll
            for (int i = 0; i < 4; i++) {
                int idx = tid + i * 256;
                int m = idx >> 4, kk = idx & 15;
                Asm[kk][m] = A[(row0 + m) * 512 + k0 + kk];
                Wsm[kk][m] = W[(n0 + m) * ldw + k0 + kk];
            }
            __syncthreads();
#pragma unroll
            for (int kk = 0; kk < 16; kk++) {
                float av[4], wv4[4];
                *(float4*)av  = *(const float4*)&Asm[kk][ty << 2];
                *(float4*)wv4 = *(const float4*)&Wsm[kk][tx << 2];
#pragma unroll
                for (int i = 0; i < 4; i++)
#pragma unroll
                    for (int j = 0; j < 4; j++) acc[i][j] += av[i] * wv4[j];
            }
        }
        // epilogue: tanh + dot with wv
#pragma unroll
        for (int i = 0; i < 4; i++) {
#pragma unroll
            for (int j = 0; j < 4; j++) {
                int n = (tx << 2) + j;
                partial[i] += tanhf(acc[i][j] + addv[n]) * wv[n];
            }
        }
    }
    __syncthreads();
#pragma unroll
    for (int i = 0; i < 4; i++) red[(ty << 2) + i][tx] = partial[i];
    __syncthreads();
    if (tid < 64) {
        float s = 0.f;
#pragma unroll
        for (int j = 0; j < 16; j++) s += red[tid][j];
        int r = row0 + tid;
        if (maskidx && maskidx[r] == 0) s -= 1000.f;
        outv[r] = s;
    }
}

// ---------------- score_g: [128, 50000] = y[128,1024] @ Wo^T + Wo_b ---------
__global__ __launch_bounds__(256)
void scoreg_kernel(const float* __restrict__ y, const float* __restrict__ Wo,
                   const float* __restrict__ Wob, float* __restrict__ outg)
{
    const int n0 = blockIdx.x * 64;
    __shared__ float Ysm[16][132];
    __shared__ float Wsm[16][68];
    const int tid = threadIdx.x;
    const int ty = tid >> 4, tx = tid & 15;
    float acc[8][4];
#pragma unroll
    for (int i = 0; i < 8; i++)
#pragma unroll
        for (int j = 0; j < 4; j++) acc[i][j] = 0.f;

    for (int k0 = 0; k0 < 1024; k0 += 16) {
        __syncthreads();
#pragma unroll
        for (int i = 0; i < 8; i++) {
            int idx = tid + i * 256;
            int m = idx >> 4, kk = idx & 15;
            Ysm[kk][m] = y[m * 1024 + k0 + kk];
        }
#pragma unroll
        for (int i = 0; i < 4; i++) {
            int idx = tid + i * 256;
            int n = idx >> 4, kk = idx & 15;
            int ng = n0 + n;
            Wsm[kk][n] = (ng < VV) ? Wo[ng * 1024 + k0 + kk] : 0.f;
        }
        __syncthreads();
#pragma unroll
        for (int kk = 0; kk < 16; kk++) {
            float yv[8], wv4[4];
            *(float4*)&yv[0] = *(const float4*)&Ysm[kk][ty * 8];
            *(float4*)&yv[4] = *(const float4*)&Ysm[kk][ty * 8 + 4];
            *(float4*)wv4    = *(const float4*)&Wsm[kk][tx << 2];
#pragma unroll
            for (int i = 0; i < 8; i++)
#pragma unroll
                for (int j = 0; j < 4; j++) acc[i][j] += yv[i] * wv4[j];
        }
    }
#pragma unroll
    for (int i = 0; i < 8; i++) {
        int m = ty * 8 + i;
#pragma unroll
        for (int j = 0; j < 4; j++) {
            int n = n0 + (tx << 2) + j;
            if (n < VV) outg[m * VV + n] = acc[i][j] + Wob[n];
        }
    }
}

// ---------------- attn softmax over S ----------------
__global__ __launch_bounds__(256)
void softmax_s_kernel(const float* __restrict__ e, float* __restrict__ w)
{
    int b = blockIdx.x, t = threadIdx.x;
    __shared__ float sm[256];
    __shared__ float bc;
    float x = e[b * SS + t];
    sm[t] = x; __syncthreads();
    for (int o = 128; o > 0; o >>= 1) { if (t < o) sm[t] = fmaxf(sm[t], sm[t + o]); __syncthreads(); }
    if (t == 0) bc = sm[0];
    __syncthreads();
    float ex = expf(x - bc);
    __syncthreads();
    sm[t] = ex; __syncthreads();
    for (int o = 128; o > 0; o >>= 1) { if (t < o) sm[t] += sm[t + o]; __syncthreads(); }
    if (t == 0) bc = sm[0];
    __syncthreads();
    w[b * SS + t] = ex / bc;
}

// ---------------- context = sum_s attnw * encoded  (into y[:,H:]) ----------
__global__ __launch_bounds__(512)
void context_kernel(const float* __restrict__ aw, const float* __restrict__ enc,
                    float* __restrict__ y)
{
    int b = blockIdx.x, h = threadIdx.x;
    __shared__ float c[256];
    if (h < 256) c[h] = aw[b * SS + h];
    __syncthreads();
    float acc = 0.f;
    const float* eb = enc + (size_t)b * SS * HH + h;
#pragma unroll 4
    for (int s = 0; s < SS; s++) acc += c[s] * eb[s * HH];
    y[b * (2 * HH) + HH + h] = acc;
}

// ---------------- row max / sumexp over concat(score_g, score_c) ------------
__global__ __launch_bounds__(256)
void rowmax_kernel(const float* __restrict__ g, const float* __restrict__ c,
                   float* __restrict__ mout)
{
    int b = blockIdx.x, t = threadIdx.x;
    float mx = -1e30f;
    const float* gb = g + (size_t)b * VV;
    for (int j = t; j < VV; j += 256) mx = fmaxf(mx, gb[j]);
    mx = fmaxf(mx, c[b * SS + t]);
    __shared__ float sm[256];
    sm[t] = mx; __syncthreads();
    for (int o = 128; o > 0; o >>= 1) { if (t < o) sm[t] = fmaxf(sm[t], sm[t + o]); __syncthreads(); }
    if (t == 0) mout[b] = sm[0];
}

__global__ __launch_bounds__(256)
void rowsum_kernel(const float* __restrict__ g, const float* __restrict__ c,
                   const float* __restrict__ m, float* __restrict__ zout)
{
    int b = blockIdx.x, t = threadIdx.x;
    float mb = m[b];
    float s = 0.f;
    const float* gb = g + (size_t)b * VV;
    for (int j = t; j < VV; j += 256) s += expf(gb[j] - mb);
    s += expf(c[b * SS + t] - mb);
    __shared__ float sm[256];
    sm[t] = s; __syncthreads();
    for (int o = 128; o > 0; o >>= 1) { if (t < o) sm[t] += sm[t + o]; __syncthreads(); }
    if (t == 0) zout[b] = sm[0];
}

// ---------------- write prob_g_ext into out ----------------
__global__ __launch_bounds__(256)
void write_outg_kernel(const float* __restrict__ g, const float* __restrict__ m,
                       const float* __restrict__ Z, float* __restrict__ out)
{
    int i = blockIdx.x * 256 + threadIdx.x;
    if (i >= BB * VEXT) return;
    int b = i / VEXT;
    int j = i - b * VEXT;
    out[i] = (j < VV) ? expf(g[(size_t)b * VV + j] - m[b]) / Z[b] : 1e-4f;
}

// ---------------- prob_c + global sum ----------------
__global__ __launch_bounds__(256)
void probc_kernel(const float* __restrict__ c, const float* __restrict__ m,
                  const float* __restrict__ Z, float* __restrict__ pc,
                  float* __restrict__ pcsum)
{
    int b = blockIdx.x, t = threadIdx.x;
    float p = expf(c[b * SS + t] - m[b]) / Z[b];
    pc[b * SS + t] = p;
    __shared__ float sm[256];
    sm[t] = p; __syncthreads();
    for (int o = 128; o > 0; o >>= 1) { if (t < o) sm[t] += sm[t + o]; __syncthreads(); }
    if (t == 0) atomicAdd(pcsum, sm[0]);
}

__global__ void zero_pcsum_kernel(float* p) { *p = 0.f; }

// ---------------- scatter prob_c into out ----------------
__global__ __launch_bounds__(256)
void scatter_kernel(const int* __restrict__ eidx, const float* __restrict__ pc,
                    float* __restrict__ out)
{
    int i = blockIdx.x * 256 + threadIdx.x;
    if (i >= BB * SS) return;
    int b = i >> 8;
    atomicAdd(&out[b * VEXT + eidx[i]], pc[i]);
}

// ---------------- weighted_new ----------------
__global__ __launch_bounds__(512)
void weighted_kernel(const int* __restrict__ eidx, const int* __restrict__ iidx,
                     const float* __restrict__ pc, const float* __restrict__ enc,
                     const float* __restrict__ pcsum, float* __restrict__ outw)
{
    int b = blockIdx.x, t = threadIdx.x;
    __shared__ float coef[256];
    __shared__ int cnt;
    if (t == 0) cnt = 0;
    __syncthreads();
    if (t < 256) {
        int match = (eidx[b * SS + t] == iidx[b]);
        coef[t] = match ? pc[b * SS + t] : 0.f;
        if (match) atomicAdd(&cnt, 1);
    }
    __syncthreads();
    float scale = 1.f / (*pcsum);
    if (cnt > 1) scale /= (float)cnt;
    float acc = 0.f;
    const float* eb = enc + (size_t)b * SS * HH + t;
#pragma unroll 4
    for (int s = 0; s < SS; s++) acc += coef[s] * eb[s * HH];
    outw[b * HH + t] = acc * scale;
}

// =========================== launch ===========================
extern "C" void kernel_launch(void* const* d_in, const int* in_sizes, int n_in,
                              void* d_out, int out_size)
{
    const int*   input_idx   = (const int*)  d_in[0];
    const float* encoded     = (const float*)d_in[1];
    const int*   encoded_idx = (const int*)  d_in[2];
    const float* prev_state  = (const float*)d_in[3];
    const float* embed_table = (const float*)d_in[5];
    const float* Ws_w        = (const float*)d_in[6];
    const float* Ws_b        = (const float*)d_in[7];
    const float* gru_Wih     = (const float*)d_in[8];
    const float* gru_Whh     = (const float*)d_in[9];
    const float* gru_bih     = (const float*)d_in[10];
    const float* gru_bhh     = (const float*)d_in[11];
    const float* attn_W      = (const float*)d_in[12];
    const float* attn_b      = (const float*)d_in[13];
    const float* attn_v      = (const float*)d_in[14];
    const float* Wo_w        = (const float*)d_in[15];
    const float* Wo_b        = (const float*)d_in[16];
    const float* Wc_w        = (const float*)d_in[17];
    const float* Wc_b        = (const float*)d_in[18];

    float* out          = (float*)d_out;                 // [B, VEXT]
    float* out_state    = out + (size_t)BB * VEXT;       // [B, H]
    float* out_weighted = out_state + BB * HH;           // [B, H]

    float* sc = nullptr;
    cudaGetSymbolAddress((void**)&sc, g_scratch);
    float* xemb   = sc + OFF_XEMB;
    float* prev   = sc + OFF_PREV;
    float* gi     = sc + OFF_GI;
    float* gh     = sc + OFF_GH;
    float* state  = sc + OFF_STATE;
    float* satt   = sc + OFF_SATT;
    float* energy = sc + OFF_ENERGY;
    float* attnw  = sc + OFF_ATTNW;
    float* yv     = sc + OFF_Y;
    float* scoreg = sc + OFF_SCOREG;
    float* scorec = sc + OFF_SCOREC;
    float* probc  = sc + OFF_PROBC;
    float* mrow   = sc + OFF_M;
    float* zrow   = sc + OFF_Z;
    float* pcsum  = sc + OFF_PCSUM;

    dim3 t16(16, 16);

    // 1. embed gather
    gather_embed<<<BB, EE>>>(input_idx, embed_table, xemb);
    // 2. prev = prev_state @ Ws_w^T + Ws_b
    gemm_nt_bias<<<dim3(HH / 16, BB / 16), t16>>>(prev_state, HH, Ws_w, HH, Ws_b,
                                                  prev, BB, HH, HH);
    // 3. gi = xemb @ Wih[:, :E]^T + bih   (zeros half of x dropped)
    gemm_nt_bias<<<dim3(3 * HH / 16, BB / 16), t16>>>(xemb, EE, gru_Wih, EE + HH,
                                                      gru_bih, gi, BB, 3 * HH, EE);
    // 4. gh = prev @ Whh^T + bhh
    gemm_nt_bias<<<dim3(3 * HH / 16, BB / 16), t16>>>(prev, HH, gru_Whh, HH,
                                                      gru_bhh, gh, BB, 3 * HH, HH);
    // 5. GRU -> state (also fills y[:, :H] and out_state)
    gru_kernel<<<(BB * HH) / 256, 256>>>(gi, gh, prev, state, yv, out_state);
    // 6. satt = state @ attn_W[:, :H]^T + attn_b
    gemm_nt_bias<<<dim3(HH / 16, BB / 16), t16>>>(state, HH, attn_W, 2 * HH,
                                                  attn_b, satt, BB, HH, HH);
    // 7. energy[b,s] = sum_h tanh(satt[b,h] + enc@attn_W2^T) * attn_v[h]
    fused_tanh_dot<<<(BB * SS) / 64, 256>>>(encoded, attn_W + HH, 2 * HH,
                                            satt, 1, attn_v, 0, nullptr, HH, energy);
    // 8. softmax over S
    softmax_s_kernel<<<BB, SS>>>(energy, attnw);
    // 9. context -> y[:, H:]
    context_kernel<<<BB, HH>>>(attnw, encoded, yv);
    // 10. score_g = y @ Wo^T + Wo_b
    scoreg_kernel<<<(VV + 63) / 64, 256>>>(yv, Wo_w, Wo_b, scoreg);
    // 11. score_c[b,s] = sum_k tanh(enc@Wc^T + Wc_b) * y[b,k]  (+ mask)
    fused_tanh_dot<<<(BB * SS) / 64, 256>>>(encoded, Wc_w, HH,
                                            Wc_b, 0, yv, 1, encoded_idx,
                                            2 * HH, scorec);
    // 12. softmax over concat(score_g, score_c)
    rowmax_kernel<<<BB, 256>>>(scoreg, scorec, mrow);
    rowsum_kernel<<<BB, 256>>>(scoreg, scorec, mrow, zrow);
    write_outg_kernel<<<(BB * VEXT + 255) / 256, 256>>>(scoreg, mrow, zrow, out);
    zero_pcsum_kernel<<<1, 1>>>(pcsum);
    probc_kernel<<<BB, SS>>>(scorec, mrow, zrow, probc, pcsum);
    // 13. scatter prob_c into out
    scatter_kernel<<<(BB * SS) / 256, 256>>>(encoded_idx, probc, out);
    // 14. weighted_new
    weighted_kernel<<<BB, HH>>>(encoded_idx, input_idx, probc, encoded,
                                pcsum, out_weighted);
}